// round 3
// baseline (speedup 1.0000x reference)
#include <cuda_runtime.h>
#include <cstdint>

// Problem constants
#define NS_PER   12500
#define AEVD     1008
#define D1       256
#define D2       192
#define D3       160
#define ENS      8
#define NSPECIES 4
#define TM       128
#define NTILES   ((NS_PER + TM - 1) / TM)   // 98

// Layer-1 staging
#define KB1    24
#define NC1    (AEVD / KB1)      // 42
#define A_LD   28                // 24 + 4 pad
#define B1_LD  264               // 256 + 8 pad
// Layer-2/3 staging
#define KB23   32
#define B2_LD  200               // 192 + 8
#define B3_LD  168               // 160 + 8
#define H_LD   264

#define SM_H      (TM * H_LD)          // 33792 floats
#define SM_A_HALF (TM * A_LD)          // 3584
#define SM_A      (2 * SM_A_HALF)      // 7168
#define BBUF      6400                 // max(24*264=6336, 32*200=6400, 32*168=5376)
#define SM_B      (2 * BBUF)           // 12800
#define SM_FLOATS (SM_H + SM_A + SM_B + 128 + 256)
#define SMEM_BYTES (SM_FLOATS * 4)     // 216,576 bytes

__device__ double g_scratch;

__device__ __forceinline__ uint32_t f2tf32(float x) {
    uint32_t r;
    asm("cvt.rna.tf32.f32 %0, %1;" : "=r"(r) : "f"(x));
    return r;
}

__device__ __forceinline__ void split2(float x, uint32_t& hi, uint32_t& lo) {
    uint32_t h = f2tf32(x);
    hi = h;
    lo = __float_as_uint(x - __uint_as_float(h));  // residual, fed raw (HW truncates)
}

__device__ __forceinline__ float celu01(float x) {
    return x > 0.f ? x : 0.1f * (__expf(x * 10.f) - 1.f);
}

__device__ __forceinline__ void mma8(float d[4], const uint32_t a[4], const uint32_t b[2]) {
    asm volatile(
        "mma.sync.aligned.m16n8k8.row.col.f32.tf32.tf32.f32 "
        "{%0,%1,%2,%3},{%4,%5,%6,%7},{%8,%9},{%0,%1,%2,%3};\n"
        : "+f"(d[0]), "+f"(d[1]), "+f"(d[2]), "+f"(d[3])
        : "r"(a[0]), "r"(a[1]), "r"(a[2]), "r"(a[3]), "r"(b[0]), "r"(b[1]));
}

__device__ __forceinline__ uint32_t smem_u32(const void* p) {
    return (uint32_t)__cvta_generic_to_shared(p);
}

__device__ __forceinline__ void cp16(uint32_t dst, const float* src, int szbytes) {
    asm volatile("cp.async.ca.shared.global [%0], [%1], 16, %2;\n"
                 :: "r"(dst), "l"(src), "r"(szbytes));
}
#define CP_COMMIT()  asm volatile("cp.async.commit_group;\n" ::)
#define CP_WAIT1()   asm volatile("cp.async.wait_group 1;\n" ::)
#define CP_WAIT0()   asm volatile("cp.async.wait_group 0;\n" ::)

__global__ void __launch_bounds__(256, 1)
ani_fused_kernel(const float* __restrict__ aev,
                 const float* __restrict__ W1, const float* __restrict__ B1,
                 const float* __restrict__ W2, const float* __restrict__ B2,
                 const float* __restrict__ W3, const float* __restrict__ B3,
                 const float* __restrict__ W4, const float* __restrict__ B4,
                 const int*   __restrict__ idx)
{
    extern __shared__ float sm[];
    float* hbuf   = sm;                      // [128][264] activations (fp32)
    float* As     = sm + SM_H;               // 2 x [128][28] layer1 A chunks
    float* Bs     = As + SM_A;               // 2 x [6400] weight chunks
    int*   rowIdx = (int*)(Bs + SM_B);       // [128]
    float* red    = (float*)(rowIdx + 128);  // [256]

    const int e    = blockIdx.x;
    const int tile = blockIdx.y;
    const int s    = blockIdx.z;
    const int se   = s * ENS + e;

    const int tid  = threadIdx.x;
    const int lane = tid & 31;
    const int warp = tid >> 5;
    const int gid  = lane >> 2;
    const int tig  = lane & 3;
    const int wm   = warp & 1;
    const int wn   = warp >> 1;
    const int mB   = wm * 64;

    const int tileBase = tile * TM;
    const int valid    = min(TM, NS_PER - tileBase);

    if (tid < TM)
        rowIdx[tid] = (tid < valid) ? idx[s * NS_PER + tileBase + tid] : -1;
    __syncthreads();

    const float* W1g = W1 + (size_t)se * AEVD * D1;
    const float* W2g = W2 + (size_t)se * D1 * D2;
    const float* W3g = W3 + (size_t)se * D2 * D3;

    // ---------------- chunk issue helpers (cp.async) ----------------
    auto issue1 = [&](int kc, int buf) {
        float* Ad = As + buf * SM_A_HALF;
        float* Bd = Bs + buf * BBUF;
        #pragma unroll
        for (int it = 0; it < 3; ++it) {            // A: 768 float4s
            int flat = tid + it * 256;
            int r  = flat / 6;
            int c4 = (flat % 6) * 4;
            int g  = rowIdx[r];
            const float* src = aev + (g >= 0 ? (size_t)g * AEVD + kc * KB1 + c4 : 0);
            cp16(smem_u32(Ad + r * A_LD + c4), src, g >= 0 ? 16 : 0);
        }
        #pragma unroll
        for (int it = 0; it < 6; ++it) {            // B: 24x256 = 1536 float4s
            int flat = tid + it * 256;
            int kk = flat / 64;
            int c4 = (flat % 64) * 4;
            cp16(smem_u32(Bd + kk * B1_LD + c4),
                 W1g + (size_t)(kc * KB1 + kk) * D1 + c4, 16);
        }
        CP_COMMIT();
    };
    auto issue2 = [&](int kc, int buf) {
        float* Bd = Bs + buf * BBUF;
        #pragma unroll
        for (int it = 0; it < 6; ++it) {            // 32x192 = 1536 float4s
            int flat = tid + it * 256;
            int kk = flat / 48;
            int c4 = (flat % 48) * 4;
            cp16(smem_u32(Bd + kk * B2_LD + c4),
                 W2g + (size_t)(kc * KB23 + kk) * D2 + c4, 16);
        }
        CP_COMMIT();
    };
    auto issue3 = [&](int kc, int buf) {
        float* Bd = Bs + buf * BBUF;
        #pragma unroll
        for (int it = 0; it < 5; ++it) {            // 32x160 = 1280 float4s
            int flat = tid + it * 256;
            int kk = flat / 40;
            int c4 = (flat % 40) * 4;
            cp16(smem_u32(Bd + kk * B3_LD + c4),
                 W3g + (size_t)(kc * KB23 + kk) * D3 + c4, 16);
        }
        CP_COMMIT();
    };

    // ================= Layer 1: [128 x 1008] @ [1008 x 256] =================
    {
        const int nB = wn * 64;
        float acc[4][8][4];
        #pragma unroll
        for (int mi = 0; mi < 4; mi++)
            #pragma unroll
            for (int j = 0; j < 8; j++)
                #pragma unroll
                for (int q = 0; q < 4; q++) acc[mi][j][q] = 0.f;

        issue1(0, 0);
        for (int kc = 0; kc < NC1; ++kc) {
            if (kc + 1 < NC1) { issue1(kc + 1, (kc + 1) & 1); CP_WAIT1(); }
            else              { CP_WAIT0(); }
            __syncthreads();
            const float* Ad = As + (kc & 1) * SM_A_HALF;
            const float* Bd = Bs + (kc & 1) * BBUF;
            #pragma unroll
            for (int ks = 0; ks < KB1 / 8; ++ks) {
                int k0 = ks * 8;
                uint32_t ah[4][4], al[4][4];
                #pragma unroll
                for (int mi = 0; mi < 4; mi++) {
                    int r = mB + mi * 16 + gid;
                    split2(Ad[r * A_LD + k0 + tig],            ah[mi][0], al[mi][0]);
                    split2(Ad[(r + 8) * A_LD + k0 + tig],      ah[mi][1], al[mi][1]);
                    split2(Ad[r * A_LD + k0 + tig + 4],        ah[mi][2], al[mi][2]);
                    split2(Ad[(r + 8) * A_LD + k0 + tig + 4],  ah[mi][3], al[mi][3]);
                }
                #pragma unroll
                for (int j = 0; j < 8; j++) {
                    uint32_t bh[2], bl[2];
                    split2(Bd[(k0 + tig) * B1_LD + nB + j * 8 + gid],     bh[0], bl[0]);
                    split2(Bd[(k0 + tig + 4) * B1_LD + nB + j * 8 + gid], bh[1], bl[1]);
                    #pragma unroll
                    for (int mi = 0; mi < 4; mi++) {
                        mma8(acc[mi][j], ah[mi], bh);
                        mma8(acc[mi][j], al[mi], bh);
                        mma8(acc[mi][j], ah[mi], bl);
                    }
                }
            }
            __syncthreads();
        }
        // Epilogue: bias + CELU -> hbuf (fp32, no rounding)
        const float* b1g = B1 + (size_t)se * D1;
        #pragma unroll
        for (int mi = 0; mi < 4; mi++) {
            int r0 = mB + mi * 16 + gid;
            #pragma unroll
            for (int j = 0; j < 8; j++) {
                int c = nB + j * 8 + tig * 2;
                float bb0 = b1g[c], bb1 = b1g[c + 1];
                hbuf[r0 * H_LD + c]           = celu01(acc[mi][j][0] + bb0);
                hbuf[r0 * H_LD + c + 1]       = celu01(acc[mi][j][1] + bb1);
                hbuf[(r0 + 8) * H_LD + c]     = celu01(acc[mi][j][2] + bb0);
                hbuf[(r0 + 8) * H_LD + c + 1] = celu01(acc[mi][j][3] + bb1);
            }
        }
    }

    // ================= Layer 2: [128 x 256] @ [256 x 192] =================
    {
        const int nB = wn * 48;
        float acc[4][6][4];
        #pragma unroll
        for (int mi = 0; mi < 4; mi++)
            #pragma unroll
            for (int j = 0; j < 6; j++)
                #pragma unroll
                for (int q = 0; q < 4; q++) acc[mi][j][q] = 0.f;

        issue2(0, 0);
        for (int kc = 0; kc < D1 / KB23; ++kc) {        // 8 chunks
            if (kc + 1 < D1 / KB23) { issue2(kc + 1, (kc + 1) & 1); CP_WAIT1(); }
            else                    { CP_WAIT0(); }
            __syncthreads();
            const float* Bd = Bs + (kc & 1) * BBUF;
            #pragma unroll
            for (int ks = 0; ks < KB23 / 8; ++ks) {
                int kg = kc * KB23 + ks * 8;
                int kl = ks * 8;
                uint32_t ah[4][4], al[4][4];
                #pragma unroll
                for (int mi = 0; mi < 4; mi++) {
                    int r = mB + mi * 16 + gid;
                    split2(hbuf[r * H_LD + kg + tig],            ah[mi][0], al[mi][0]);
                    split2(hbuf[(r + 8) * H_LD + kg + tig],      ah[mi][1], al[mi][1]);
                    split2(hbuf[r * H_LD + kg + tig + 4],        ah[mi][2], al[mi][2]);
                    split2(hbuf[(r + 8) * H_LD + kg + tig + 4],  ah[mi][3], al[mi][3]);
                }
                #pragma unroll
                for (int j = 0; j < 6; j++) {
                    uint32_t bh[2], bl[2];
                    split2(Bd[(kl + tig) * B2_LD + nB + j * 8 + gid],     bh[0], bl[0]);
                    split2(Bd[(kl + tig + 4) * B2_LD + nB + j * 8 + gid], bh[1], bl[1]);
                    #pragma unroll
                    for (int mi = 0; mi < 4; mi++) {
                        mma8(acc[mi][j], ah[mi], bh);
                        mma8(acc[mi][j], al[mi], bh);
                        mma8(acc[mi][j], ah[mi], bl);
                    }
                }
            }
            __syncthreads();
        }
        __syncthreads();  // all reads of h1 done before overwrite
        const float* b2g = B2 + (size_t)se * D2;
        #pragma unroll
        for (int mi = 0; mi < 4; mi++) {
            int r0 = mB + mi * 16 + gid;
            #pragma unroll
            for (int j = 0; j < 6; j++) {
                int c = nB + j * 8 + tig * 2;
                float bb0 = b2g[c], bb1 = b2g[c + 1];
                hbuf[r0 * H_LD + c]           = celu01(acc[mi][j][0] + bb0);
                hbuf[r0 * H_LD + c + 1]       = celu01(acc[mi][j][1] + bb1);
                hbuf[(r0 + 8) * H_LD + c]     = celu01(acc[mi][j][2] + bb0);
                hbuf[(r0 + 8) * H_LD + c + 1] = celu01(acc[mi][j][3] + bb1);
            }
        }
    }

    // ================= Layer 3: [128 x 192] @ [192 x 160] =================
    {
        const int nB = wn * 40;
        float acc[4][5][4];
        #pragma unroll
        for (int mi = 0; mi < 4; mi++)
            #pragma unroll
            for (int j = 0; j < 5; j++)
                #pragma unroll
                for (int q = 0; q < 4; q++) acc[mi][j][q] = 0.f;

        issue3(0, 0);
        for (int kc = 0; kc < D2 / KB23; ++kc) {        // 6 chunks
            if (kc + 1 < D2 / KB23) { issue3(kc + 1, (kc + 1) & 1); CP_WAIT1(); }
            else                    { CP_WAIT0(); }
            __syncthreads();
            const float* Bd = Bs + (kc & 1) * BBUF;
            #pragma unroll
            for (int ks = 0; ks < KB23 / 8; ++ks) {
                int kg = kc * KB23 + ks * 8;
                int kl = ks * 8;
                uint32_t ah[4][4], al[4][4];
                #pragma unroll
                for (int mi = 0; mi < 4; mi++) {
                    int r = mB + mi * 16 + gid;
                    split2(hbuf[r * H_LD + kg + tig],            ah[mi][0], al[mi][0]);
                    split2(hbuf[(r + 8) * H_LD + kg + tig],      ah[mi][1], al[mi][1]);
                    split2(hbuf[r * H_LD + kg + tig + 4],        ah[mi][2], al[mi][2]);
                    split2(hbuf[(r + 8) * H_LD + kg + tig + 4],  ah[mi][3], al[mi][3]);
                }
                #pragma unroll
                for (int j = 0; j < 5; j++) {
                    uint32_t bh[2], bl[2];
                    split2(Bd[(kl + tig) * B3_LD + nB + j * 8 + gid],     bh[0], bl[0]);
                    split2(Bd[(kl + tig + 4) * B3_LD + nB + j * 8 + gid], bh[1], bl[1]);
                    #pragma unroll
                    for (int mi = 0; mi < 4; mi++) {
                        mma8(acc[mi][j], ah[mi], bh);
                        mma8(acc[mi][j], al[mi], bh);
                        mma8(acc[mi][j], ah[mi], bl);
                    }
                }
            }
            __syncthreads();
        }
        __syncthreads();  // all reads of h2 done before overwrite
        const float* b3g = B3 + (size_t)se * D3;
        #pragma unroll
        for (int mi = 0; mi < 4; mi++) {
            int r0 = mB + mi * 16 + gid;
            #pragma unroll
            for (int j = 0; j < 5; j++) {
                int c = nB + j * 8 + tig * 2;
                float bb0 = b3g[c], bb1 = b3g[c + 1];
                hbuf[r0 * H_LD + c]           = celu01(acc[mi][j][0] + bb0);
                hbuf[r0 * H_LD + c + 1]       = celu01(acc[mi][j][1] + bb1);
                hbuf[(r0 + 8) * H_LD + c]     = celu01(acc[mi][j][2] + bb0);
                hbuf[(r0 + 8) * H_LD + c + 1] = celu01(acc[mi][j][3] + bb1);
            }
        }
    }

    // ========== Layer 4 + reduction: sum_m (h3 . w4) + valid*b4 ==========
    __syncthreads();
    float v = 0.f;
    if (tid < D3) {
        float cs = 0.f;
        for (int r = 0; r < valid; ++r) cs += hbuf[r * H_LD + tid];
        v = cs * W4[(size_t)se * D3 + tid];
    }
    red[tid] = v;
    __syncthreads();
    #pragma unroll
    for (int st = 128; st > 0; st >>= 1) {
        if (tid < st) red[tid] += red[tid + st];
        __syncthreads();
    }
    if (tid == 0)
        atomicAdd(&g_scratch, (double)(red[0] + (float)valid * B4[se]));
}

__global__ void init_kernel() { g_scratch = 0.0; }

__global__ void fin_kernel(float* out) { out[0] = (float)(g_scratch * (1.0 / ENS)); }

extern "C" void kernel_launch(void* const* d_in, const int* in_sizes, int n_in,
                              void* d_out, int out_size)
{
    // Identify inputs by element count (robust to metadata ordering).
    const float *aev = 0, *W1 = 0, *B1 = 0, *W2 = 0, *B2 = 0,
                *W3 = 0, *B3 = 0, *W4 = 0, *B4 = 0;
    const int *idx = 0;
    int n5120 = 0, n50000 = 0;
    for (int i = 0; i < n_in; ++i) {
        switch (in_sizes[i]) {
            case 50400000: aev = (const float*)d_in[i]; break;
            case 8257536:  W1  = (const float*)d_in[i]; break;
            case 8192:     B1  = (const float*)d_in[i]; break;
            case 1572864:  W2  = (const float*)d_in[i]; break;
            case 6144:     B2  = (const float*)d_in[i]; break;
            case 983040:   W3  = (const float*)d_in[i]; break;
            case 5120:
                if (n5120++ == 0) B3 = (const float*)d_in[i];
                else              W4 = (const float*)d_in[i];
                break;
            case 32:       B4  = (const float*)d_in[i]; break;
            case 50000:
                if (n50000++ == 0) { /* species (unused) */ }
                else idx = (const int*)d_in[i];
                break;
            default: break;
        }
    }

    cudaFuncSetAttribute(ani_fused_kernel,
                         cudaFuncAttributeMaxDynamicSharedMemorySize, SMEM_BYTES);

    init_kernel<<<1, 1>>>();
    dim3 grid(ENS, NTILES, NSPECIES);   // e fastest -> AEV rows reused in L2
    ani_fused_kernel<<<grid, 256, SMEM_BYTES>>>(aev, W1, B1, W2, B2, W3, B3, W4, B4, idx);
    fin_kernel<<<1, 1>>>((float*)d_out);
}

// round 4
// speedup vs baseline: 1.3411x; 1.3411x over previous
#include <cuda_runtime.h>
#include <cstdint>

// Problem constants
#define NS_PER   12500
#define AEVD     1008
#define D1       256
#define D2       192
#define D3       160
#define ENS      8
#define NSPECIES 4
#define TM       128
#define NTILES   ((NS_PER + TM - 1) / TM)   // 98

// Layer-1 staging: K chunks of 16 (63 chunks, one m16n8k16 step each)
#define KB1    16
#define NC1    (AEVD / KB1)      // 63
#define A_LD   20                // 16 + 4 pad
#define B1_LD  264               // 256 + 8 pad
// Layer-2/3 staging: K chunks of 32 (two k16 steps)
#define KB23   32
#define B2_LD  200               // 192 + 8
#define B3_LD  168               // 160 + 8
#define H_LD   264

#define SM_H      (TM * H_LD)          // 33792 floats
#define SM_A_HALF (TM * A_LD)          // 2560
#define SM_A      (2 * SM_A_HALF)      // 5120
#define BBUF      6400                 // max(16*264=4224, 32*200=6400, 32*168=5376)
#define SM_B      (2 * BBUF)           // 12800
#define SM_FLOATS (SM_H + SM_A + SM_B + 128 + 256)
#define SMEM_BYTES (SM_FLOATS * 4)     // 208,384 bytes

__device__ double g_scratch;

// Split a pair of fp32 into packed bf16 hi-plane and lo-plane registers.
// reg layout: low 16 bits = element0, high 16 bits = element1 (f16x2 convention).
__device__ __forceinline__ void splitbf(float x0, float x1, uint32_t& hi, uint32_t& lo) {
    uint32_t h;
    asm("cvt.rn.bf16x2.f32 %0, %1, %2;" : "=r"(h) : "f"(x1), "f"(x0));
    float h0 = __uint_as_float(h << 16);
    float h1 = __uint_as_float(h & 0xFFFF0000u);
    float l0 = x0 - h0;
    float l1 = x1 - h1;
    asm("cvt.rn.bf16x2.f32 %0, %1, %2;" : "=r"(lo) : "f"(l1), "f"(l0));
    hi = h;
}

__device__ __forceinline__ float celu01(float x) {
    return x > 0.f ? x : 0.1f * (__expf(x * 10.f) - 1.f);
}

__device__ __forceinline__ void mma16(float d[4], const uint32_t a[4], const uint32_t b[2]) {
    asm volatile(
        "mma.sync.aligned.m16n8k16.row.col.f32.bf16.bf16.f32 "
        "{%0,%1,%2,%3},{%4,%5,%6,%7},{%8,%9},{%0,%1,%2,%3};\n"
        : "+f"(d[0]), "+f"(d[1]), "+f"(d[2]), "+f"(d[3])
        : "r"(a[0]), "r"(a[1]), "r"(a[2]), "r"(a[3]), "r"(b[0]), "r"(b[1]));
}

__device__ __forceinline__ uint32_t smem_u32(const void* p) {
    return (uint32_t)__cvta_generic_to_shared(p);
}

__device__ __forceinline__ void cp16(uint32_t dst, const float* src, int szbytes) {
    asm volatile("cp.async.ca.shared.global [%0], [%1], 16, %2;\n"
                 :: "r"(dst), "l"(src), "r"(szbytes));
}
#define CP_COMMIT()  asm volatile("cp.async.commit_group;\n" ::)
#define CP_WAIT1()   asm volatile("cp.async.wait_group 1;\n" ::)
#define CP_WAIT0()   asm volatile("cp.async.wait_group 0;\n" ::)

__global__ void __launch_bounds__(256, 1)
ani_fused_kernel(const float* __restrict__ aev,
                 const float* __restrict__ W1, const float* __restrict__ B1,
                 const float* __restrict__ W2, const float* __restrict__ B2,
                 const float* __restrict__ W3, const float* __restrict__ B3,
                 const float* __restrict__ W4, const float* __restrict__ B4,
                 const int*   __restrict__ idx)
{
    extern __shared__ float sm[];
    float* hbuf   = sm;                      // [128][264] activations (fp32)
    float* As     = sm + SM_H;               // 2 x [128][20] layer1 A chunks
    float* Bs     = As + SM_A;               // 2 x [6400] weight chunks
    int*   rowIdx = (int*)(Bs + SM_B);       // [128]
    float* red    = (float*)(rowIdx + 128);  // [256]

    const int e    = blockIdx.x;
    const int tile = blockIdx.y;
    const int s    = blockIdx.z;
    const int se   = s * ENS + e;

    const int tid  = threadIdx.x;
    const int lane = tid & 31;
    const int warp = tid >> 5;
    const int gid  = lane >> 2;   // 0..7
    const int tig  = lane & 3;    // 0..3
    const int wm   = warp & 1;
    const int wn   = warp >> 1;
    const int mB   = wm * 64;

    const int tileBase = tile * TM;
    const int valid    = min(TM, NS_PER - tileBase);

    if (tid < TM)
        rowIdx[tid] = (tid < valid) ? idx[s * NS_PER + tileBase + tid] : -1;
    __syncthreads();

    const float* W1g = W1 + (size_t)se * AEVD * D1;
    const float* W2g = W2 + (size_t)se * D1 * D2;
    const float* W3g = W3 + (size_t)se * D2 * D3;

    // ---------------- chunk issue helpers (cp.async) ----------------
    auto issue1 = [&](int kc, int buf) {
        float* Ad = As + buf * SM_A_HALF;
        float* Bd = Bs + buf * BBUF;
        #pragma unroll
        for (int it = 0; it < 2; ++it) {            // A: 128x16 = 512 float4s
            int flat = tid + it * 256;
            int r  = flat >> 2;
            int c4 = (flat & 3) * 4;
            int g  = rowIdx[r];
            const float* src = aev + (g >= 0 ? (size_t)g * AEVD + kc * KB1 + c4 : 0);
            cp16(smem_u32(Ad + r * A_LD + c4), src, g >= 0 ? 16 : 0);
        }
        #pragma unroll
        for (int it = 0; it < 4; ++it) {            // B: 16x256 = 1024 float4s
            int flat = tid + it * 256;
            int kk = flat >> 6;
            int c4 = (flat & 63) * 4;
            cp16(smem_u32(Bd + kk * B1_LD + c4),
                 W1g + (size_t)(kc * KB1 + kk) * D1 + c4, 16);
        }
        CP_COMMIT();
    };
    auto issue2 = [&](int kc, int buf) {
        float* Bd = Bs + buf * BBUF;
        #pragma unroll
        for (int it = 0; it < 6; ++it) {            // 32x192 = 1536 float4s
            int flat = tid + it * 256;
            int kk = flat / 48;
            int c4 = (flat % 48) * 4;
            cp16(smem_u32(Bd + kk * B2_LD + c4),
                 W2g + (size_t)(kc * KB23 + kk) * D2 + c4, 16);
        }
        CP_COMMIT();
    };
    auto issue3 = [&](int kc, int buf) {
        float* Bd = Bs + buf * BBUF;
        #pragma unroll
        for (int it = 0; it < 5; ++it) {            // 32x160 = 1280 float4s
            int flat = tid + it * 256;
            int kk = flat / 40;
            int c4 = (flat % 40) * 4;
            cp16(smem_u32(Bd + kk * B3_LD + c4),
                 W3g + (size_t)(kc * KB23 + kk) * D3 + c4, 16);
        }
        CP_COMMIT();
    };

    // ================= Layer 1: [128 x 1008] @ [1008 x 256] =================
    {
        const int nB = wn * 64;
        float acc[4][8][4];
        #pragma unroll
        for (int mi = 0; mi < 4; mi++)
            #pragma unroll
            for (int j = 0; j < 8; j++)
                #pragma unroll
                for (int q = 0; q < 4; q++) acc[mi][j][q] = 0.f;

        issue1(0, 0);
        for (int kc = 0; kc < NC1; ++kc) {
            if (kc + 1 < NC1) { issue1(kc + 1, (kc + 1) & 1); CP_WAIT1(); }
            else              { CP_WAIT0(); }
            __syncthreads();
            const float* Ad = As + (kc & 1) * SM_A_HALF;
            const float* Bd = Bs + (kc & 1) * BBUF;

            uint32_t ah[4][4], al[4][4];
            #pragma unroll
            for (int mi = 0; mi < 4; mi++) {
                int r = mB + mi * 16 + gid;
                float2 p0 = *(const float2*)(Ad + r * A_LD + 2 * tig);
                float2 p1 = *(const float2*)(Ad + (r + 8) * A_LD + 2 * tig);
                float2 p2 = *(const float2*)(Ad + r * A_LD + 8 + 2 * tig);
                float2 p3 = *(const float2*)(Ad + (r + 8) * A_LD + 8 + 2 * tig);
                splitbf(p0.x, p0.y, ah[mi][0], al[mi][0]);
                splitbf(p1.x, p1.y, ah[mi][1], al[mi][1]);
                splitbf(p2.x, p2.y, ah[mi][2], al[mi][2]);
                splitbf(p3.x, p3.y, ah[mi][3], al[mi][3]);
            }
            #pragma unroll
            for (int j = 0; j < 8; j++) {
                int n = nB + j * 8 + gid;
                float q0 = Bd[(2 * tig) * B1_LD + n];
                float q1 = Bd[(2 * tig + 1) * B1_LD + n];
                float q2 = Bd[(2 * tig + 8) * B1_LD + n];
                float q3 = Bd[(2 * tig + 9) * B1_LD + n];
                uint32_t bh[2], bl[2];
                splitbf(q0, q1, bh[0], bl[0]);
                splitbf(q2, q3, bh[1], bl[1]);
                #pragma unroll
                for (int mi = 0; mi < 4; mi++) {
                    mma16(acc[mi][j], ah[mi], bh);
                    mma16(acc[mi][j], al[mi], bh);
                    mma16(acc[mi][j], ah[mi], bl);
                }
            }
            __syncthreads();
        }
        // Epilogue: bias + CELU -> hbuf (fp32)
        const float* b1g = B1 + (size_t)se * D1;
        #pragma unroll
        for (int mi = 0; mi < 4; mi++) {
            int r0 = mB + mi * 16 + gid;
            #pragma unroll
            for (int j = 0; j < 8; j++) {
                int c = nB + j * 8 + tig * 2;
                float bb0 = b1g[c], bb1 = b1g[c + 1];
                hbuf[r0 * H_LD + c]           = celu01(acc[mi][j][0] + bb0);
                hbuf[r0 * H_LD + c + 1]       = celu01(acc[mi][j][1] + bb1);
                hbuf[(r0 + 8) * H_LD + c]     = celu01(acc[mi][j][2] + bb0);
                hbuf[(r0 + 8) * H_LD + c + 1] = celu01(acc[mi][j][3] + bb1);
            }
        }
    }

    // ================= Layer 2: [128 x 256] @ [256 x 192] =================
    {
        const int nB = wn * 48;
        float acc[4][6][4];
        #pragma unroll
        for (int mi = 0; mi < 4; mi++)
            #pragma unroll
            for (int j = 0; j < 6; j++)
                #pragma unroll
                for (int q = 0; q < 4; q++) acc[mi][j][q] = 0.f;

        issue2(0, 0);
        for (int kc = 0; kc < D1 / KB23; ++kc) {        // 8 chunks
            if (kc + 1 < D1 / KB23) { issue2(kc + 1, (kc + 1) & 1); CP_WAIT1(); }
            else                    { CP_WAIT0(); }
            __syncthreads();
            const float* Bd = Bs + (kc & 1) * BBUF;
            #pragma unroll
            for (int ks = 0; ks < 2; ++ks) {            // two k16 steps
                int kg = kc * KB23 + ks * 16;
                int kl = ks * 16;
                uint32_t ah[4][4], al[4][4];
                #pragma unroll
                for (int mi = 0; mi < 4; mi++) {
                    int r = mB + mi * 16 + gid;
                    float2 p0 = *(const float2*)(hbuf + r * H_LD + kg + 2 * tig);
                    float2 p1 = *(const float2*)(hbuf + (r + 8) * H_LD + kg + 2 * tig);
                    float2 p2 = *(const float2*)(hbuf + r * H_LD + kg + 8 + 2 * tig);
                    float2 p3 = *(const float2*)(hbuf + (r + 8) * H_LD + kg + 8 + 2 * tig);
                    splitbf(p0.x, p0.y, ah[mi][0], al[mi][0]);
                    splitbf(p1.x, p1.y, ah[mi][1], al[mi][1]);
                    splitbf(p2.x, p2.y, ah[mi][2], al[mi][2]);
                    splitbf(p3.x, p3.y, ah[mi][3], al[mi][3]);
                }
                #pragma unroll
                for (int j = 0; j < 6; j++) {
                    int n = nB + j * 8 + gid;
                    float q0 = Bd[(kl + 2 * tig) * B2_LD + n];
                    float q1 = Bd[(kl + 2 * tig + 1) * B2_LD + n];
                    float q2 = Bd[(kl + 2 * tig + 8) * B2_LD + n];
                    float q3 = Bd[(kl + 2 * tig + 9) * B2_LD + n];
                    uint32_t bh[2], bl[2];
                    splitbf(q0, q1, bh[0], bl[0]);
                    splitbf(q2, q3, bh[1], bl[1]);
                    #pragma unroll
                    for (int mi = 0; mi < 4; mi++) {
                        mma16(acc[mi][j], ah[mi], bh);
                        mma16(acc[mi][j], al[mi], bh);
                        mma16(acc[mi][j], ah[mi], bl);
                    }
                }
            }
            __syncthreads();
        }
        __syncthreads();  // all reads of h1 done before overwrite
        const float* b2g = B2 + (size_t)se * D2;
        #pragma unroll
        for (int mi = 0; mi < 4; mi++) {
            int r0 = mB + mi * 16 + gid;
            #pragma unroll
            for (int j = 0; j < 6; j++) {
                int c = nB + j * 8 + tig * 2;
                float bb0 = b2g[c], bb1 = b2g[c + 1];
                hbuf[r0 * H_LD + c]           = celu01(acc[mi][j][0] + bb0);
                hbuf[r0 * H_LD + c + 1]       = celu01(acc[mi][j][1] + bb1);
                hbuf[(r0 + 8) * H_LD + c]     = celu01(acc[mi][j][2] + bb0);
                hbuf[(r0 + 8) * H_LD + c + 1] = celu01(acc[mi][j][3] + bb1);
            }
        }
    }

    // ================= Layer 3: [128 x 192] @ [192 x 160] =================
    {
        const int nB = wn * 40;
        float acc[4][5][4];
        #pragma unroll
        for (int mi = 0; mi < 4; mi++)
            #pragma unroll
            for (int j = 0; j < 5; j++)
                #pragma unroll
                for (int q = 0; q < 4; q++) acc[mi][j][q] = 0.f;

        issue3(0, 0);
        for (int kc = 0; kc < D2 / KB23; ++kc) {        // 6 chunks
            if (kc + 1 < D2 / KB23) { issue3(kc + 1, (kc + 1) & 1); CP_WAIT1(); }
            else                    { CP_WAIT0(); }
            __syncthreads();
            const float* Bd = Bs + (kc & 1) * BBUF;
            #pragma unroll
            for (int ks = 0; ks < 2; ++ks) {
                int kg = kc * KB23 + ks * 16;
                int kl = ks * 16;
                uint32_t ah[4][4], al[4][4];
                #pragma unroll
                for (int mi = 0; mi < 4; mi++) {
                    int r = mB + mi * 16 + gid;
                    float2 p0 = *(const float2*)(hbuf + r * H_LD + kg + 2 * tig);
                    float2 p1 = *(const float2*)(hbuf + (r + 8) * H_LD + kg + 2 * tig);
                    float2 p2 = *(const float2*)(hbuf + r * H_LD + kg + 8 + 2 * tig);
                    float2 p3 = *(const float2*)(hbuf + (r + 8) * H_LD + kg + 8 + 2 * tig);
                    splitbf(p0.x, p0.y, ah[mi][0], al[mi][0]);
                    splitbf(p1.x, p1.y, ah[mi][1], al[mi][1]);
                    splitbf(p2.x, p2.y, ah[mi][2], al[mi][2]);
                    splitbf(p3.x, p3.y, ah[mi][3], al[mi][3]);
                }
                #pragma unroll
                for (int j = 0; j < 5; j++) {
                    int n = nB + j * 8 + gid;
                    float q0 = Bd[(kl + 2 * tig) * B3_LD + n];
                    float q1 = Bd[(kl + 2 * tig + 1) * B3_LD + n];
                    float q2 = Bd[(kl + 2 * tig + 8) * B3_LD + n];
                    float q3 = Bd[(kl + 2 * tig + 9) * B3_LD + n];
                    uint32_t bh[2], bl[2];
                    splitbf(q0, q1, bh[0], bl[0]);
                    splitbf(q2, q3, bh[1], bl[1]);
                    #pragma unroll
                    for (int mi = 0; mi < 4; mi++) {
                        mma16(acc[mi][j], ah[mi], bh);
                        mma16(acc[mi][j], al[mi], bh);
                        mma16(acc[mi][j], ah[mi], bl);
                    }
                }
            }
            __syncthreads();
        }
        __syncthreads();  // all reads of h2 done before overwrite
        const float* b3g = B3 + (size_t)se * D3;
        #pragma unroll
        for (int mi = 0; mi < 4; mi++) {
            int r0 = mB + mi * 16 + gid;
            #pragma unroll
            for (int j = 0; j < 5; j++) {
                int c = nB + j * 8 + tig * 2;
                float bb0 = b3g[c], bb1 = b3g[c + 1];
                hbuf[r0 * H_LD + c]           = celu01(acc[mi][j][0] + bb0);
                hbuf[r0 * H_LD + c + 1]       = celu01(acc[mi][j][1] + bb1);
                hbuf[(r0 + 8) * H_LD + c]     = celu01(acc[mi][j][2] + bb0);
                hbuf[(r0 + 8) * H_LD + c + 1] = celu01(acc[mi][j][3] + bb1);
            }
        }
    }

    // ========== Layer 4 + reduction: sum_m (h3 . w4) + valid*b4 ==========
    __syncthreads();
    float v = 0.f;
    if (tid < D3) {
        float cs = 0.f;
        for (int r = 0; r < valid; ++r) cs += hbuf[r * H_LD + tid];
        v = cs * W4[(size_t)se * D3 + tid];
    }
    red[tid] = v;
    __syncthreads();
    #pragma unroll
    for (int st = 128; st > 0; st >>= 1) {
        if (tid < st) red[tid] += red[tid + st];
        __syncthreads();
    }
    if (tid == 0)
        atomicAdd(&g_scratch, (double)(red[0] + (float)valid * B4[se]));
}

__global__ void init_kernel() { g_scratch = 0.0; }

__global__ void fin_kernel(float* out) { out[0] = (float)(g_scratch * (1.0 / ENS)); }

extern "C" void kernel_launch(void* const* d_in, const int* in_sizes, int n_in,
                              void* d_out, int out_size)
{
    // Identify inputs by element count (robust to metadata ordering).
    const float *aev = 0, *W1 = 0, *B1 = 0, *W2 = 0, *B2 = 0,
                *W3 = 0, *B3 = 0, *W4 = 0, *B4 = 0;
    const int *idx = 0;
    int n5120 = 0, n50000 = 0;
    for (int i = 0; i < n_in; ++i) {
        switch (in_sizes[i]) {
            case 50400000: aev = (const float*)d_in[i]; break;
            case 8257536:  W1  = (const float*)d_in[i]; break;
            case 8192:     B1  = (const float*)d_in[i]; break;
            case 1572864:  W2  = (const float*)d_in[i]; break;
            case 6144:     B2  = (const float*)d_in[i]; break;
            case 983040:   W3  = (const float*)d_in[i]; break;
            case 5120:
                if (n5120++ == 0) B3 = (const float*)d_in[i];
                else              W4 = (const float*)d_in[i];
                break;
            case 32:       B4  = (const float*)d_in[i]; break;
            case 50000:
                if (n50000++ == 0) { /* species (unused) */ }
                else idx = (const int*)d_in[i];
                break;
            default: break;
        }
    }

    cudaFuncSetAttribute(ani_fused_kernel,
                         cudaFuncAttributeMaxDynamicSharedMemorySize, SMEM_BYTES);

    init_kernel<<<1, 1>>>();
    dim3 grid(ENS, NTILES, NSPECIES);   // e fastest -> AEV rows reused in L2
    ani_fused_kernel<<<grid, 256, SMEM_BYTES>>>(aev, W1, B1, W2, B2, W3, B3, W4, B4, idx);
    fin_kernel<<<1, 1>>>((float*)d_out);
}

// round 6
// speedup vs baseline: 1.7537x; 1.3076x over previous
#include <cuda_runtime.h>
#include <cstdint>

// ---------------- problem constants ----------------
#define NS_PER   12500
#define AEVD     1008
#define KPAD1    1024
#define D1       256
#define D2       192
#define D3       160
#define ENS      8
#define NSPECIES 4
#define TM       128
#define NTILES   98
#define NATOM    50000
#define NSE      32

#define NC1 32    // KPAD1/32
#define NC2 8     // D1/32
#define NC3 6     // D2/32

// ---------------- persistent bf16 plane scratch ----------------
__device__ uint16_t g_aevH[(size_t)NATOM * KPAD1];
__device__ uint16_t g_aevL[(size_t)NATOM * KPAD1];
__device__ uint16_t g_w1H[(size_t)NSE * D1 * KPAD1];
__device__ uint16_t g_w1L[(size_t)NSE * D1 * KPAD1];
__device__ uint16_t g_w2H[(size_t)NSE * D2 * D1];
__device__ uint16_t g_w2L[(size_t)NSE * D2 * D1];
__device__ uint16_t g_w3H[(size_t)NSE * D3 * D2];
__device__ uint16_t g_w3L[(size_t)NSE * D3 * D2];
__device__ double g_scratch;

// ---------------- smem layout (bytes) ----------------
#define RI_OFF   0                         // 128 ints
#define RED_OFF  512                       // 256 floats
#define PL       2048
#define APL(b,p) (PL + ((b)*2+(p))*10240)              // [128][40] bf16
#define BPL(b,p) (PL + 40960 + ((b)*2+(p))*20480)      // [256][40] bf16
#define HH       PL                                     // [128][264] bf16
#define HL       (PL + 67584)
#define WPL(b,p) (PL + 135168 + ((b)*2+(p))*15360)     // [192][40] bf16
#define SMEM_BYTES (PL + 135168 + 61440)               // 198656

// ---------------- helpers ----------------
__device__ __forceinline__ uint32_t cvt2(float v0, float v1) {  // v0->lo16, v1->hi16
    uint32_t r;
    asm("cvt.rn.bf16x2.f32 %0, %1, %2;" : "=r"(r) : "f"(v1), "f"(v0));
    return r;
}
__device__ __forceinline__ float lo16f(uint32_t h) { return __uint_as_float(h << 16); }
__device__ __forceinline__ float hi16f(uint32_t h) { return __uint_as_float(h & 0xFFFF0000u); }

__device__ __forceinline__ float celu01(float x) {
    return x > 0.f ? x : 0.1f * (__expf(x * 10.f) - 1.f);
}

__device__ __forceinline__ void mma16(float d[4], const uint32_t a[4], const uint32_t b[2]) {
    asm volatile(
        "mma.sync.aligned.m16n8k16.row.col.f32.bf16.bf16.f32 "
        "{%0,%1,%2,%3},{%4,%5,%6,%7},{%8,%9},{%0,%1,%2,%3};\n"
        : "+f"(d[0]), "+f"(d[1]), "+f"(d[2]), "+f"(d[3])
        : "r"(a[0]), "r"(a[1]), "r"(a[2]), "r"(a[3]), "r"(b[0]), "r"(b[1]));
}

__device__ __forceinline__ void ldm4(uint32_t* r, uint32_t addr) {
    asm volatile("ldmatrix.sync.aligned.m8n8.x4.shared.b16 {%0,%1,%2,%3}, [%4];"
                 : "=r"(r[0]), "=r"(r[1]), "=r"(r[2]), "=r"(r[3]) : "r"(addr));
}
__device__ __forceinline__ void ldm2(uint32_t* r, uint32_t addr) {
    asm volatile("ldmatrix.sync.aligned.m8n8.x2.shared.b16 {%0,%1}, [%2];"
                 : "=r"(r[0]), "=r"(r[1]) : "r"(addr));
}

__device__ __forceinline__ void cp16(uint32_t dst, const void* src, int szbytes) {
    asm volatile("cp.async.ca.shared.global [%0], [%1], 16, %2;\n"
                 :: "r"(dst), "l"(src), "r"(szbytes));
}
#define CP_COMMIT()  asm volatile("cp.async.commit_group;\n" ::)
#define CP_WAIT1()   asm volatile("cp.async.wait_group 1;\n" ::)
#define CP_WAIT0()   asm volatile("cp.async.wait_group 0;\n" ::)

// ---------------- pre-pass kernels ----------------
__global__ void prep_aev(const float* __restrict__ aev) {
    int t = blockIdx.x * 256 + threadIdx.x;            // pair index
    if (t >= NATOM * (KPAD1 / 2)) return;
    int a  = t / (KPAD1 / 2);
    int kp = t - a * (KPAD1 / 2);
    int k  = 2 * kp;
    float v0 = (k     < AEVD) ? aev[(size_t)a * AEVD + k]     : 0.f;
    float v1 = (k + 1 < AEVD) ? aev[(size_t)a * AEVD + k + 1] : 0.f;
    uint32_t h = cvt2(v0, v1);
    uint32_t l = cvt2(v0 - lo16f(h), v1 - hi16f(h));
    ((uint32_t*)g_aevH)[t] = h;
    ((uint32_t*)g_aevL)[t] = l;
}

// W [se][K][N] fp32 -> planes [se][N][Kpad] bf16 (K padded with zeros)
__global__ void prep_w(const float* __restrict__ W, uint16_t* dH, uint16_t* dL,
                       int K, int N, int Kpad) {
    int t = blockIdx.x * 256 + threadIdx.x;
    int tot = NSE * N * (Kpad / 2);
    if (t >= tot) return;
    int n  = t % N;
    int r  = t / N;
    int kp = r % (Kpad / 2);
    int se = r / (Kpad / 2);
    int k  = 2 * kp;
    float v0 = (k     < K) ? W[((size_t)se * K + k) * N + n]     : 0.f;
    float v1 = (k + 1 < K) ? W[((size_t)se * K + k + 1) * N + n] : 0.f;
    uint32_t h = cvt2(v0, v1);
    uint32_t l = cvt2(v0 - lo16f(h), v1 - hi16f(h));
    size_t di = ((size_t)se * N + n) * (Kpad / 2) + kp;
    ((uint32_t*)dH)[di] = h;
    ((uint32_t*)dL)[di] = l;
}

// ---------------- main fused kernel ----------------
__global__ void __launch_bounds__(256, 1)
ani_main(const float* __restrict__ B1, const float* __restrict__ B2,
         const float* __restrict__ B3, const float* __restrict__ W4,
         const float* __restrict__ B4, const int* __restrict__ idx)
{
    extern __shared__ char smc[];
    const uint32_t smem_base = (uint32_t)__cvta_generic_to_shared(smc);
    int*   rowIdx = (int*)(smc + RI_OFF);
    float* red    = (float*)(smc + RED_OFF);

    const int e    = blockIdx.x;
    const int tile = blockIdx.y;
    const int s    = blockIdx.z;
    const int se   = s * ENS + e;

    const int tid  = threadIdx.x;
    const int lane = tid & 31;
    const int warp = tid >> 5;
    const int gid  = lane >> 2;
    const int tig  = lane & 3;
    const int wm   = warp & 1;
    const int wn   = warp >> 1;     // 0..3
    const int mB   = wm * 64;

    // ldmatrix per-lane row/col selectors
    const int amrow = (lane & 7) + (lane & 8);        // A: row offset within 16
    const int akoff = (lane & 16) >> 1;               // A: +8 k for mats 2,3
    const int bnrow = (lane & 7) + ((lane & 16) >> 1);// B: row (n) offset
    const int bkoff = lane & 8;                       // B: +8 k for mats 1,3

    const int tileBase = tile * TM;
    const int valid    = min(TM, NS_PER - tileBase);

    if (tid < TM)
        rowIdx[tid] = (tid < valid) ? idx[s * NS_PER + tileBase + tid] : -1;
    __syncthreads();

    const float* b1g = B1 + (size_t)se * D1;
    const float* b2g = B2 + (size_t)se * D2;
    const float* b3g = B3 + (size_t)se * D3;
    const float* w4g = W4 + (size_t)se * D3;

    // ---------------- cp.async issue helpers ----------------
    auto issueA1 = [&](int kc, int b) {
        #pragma unroll
        for (int it = 0; it < 4; ++it) {
            int t = tid + it * 256;          // 0..1023
            int p   = t >> 9;
            int rem = t & 511;
            int r   = rem >> 2;
            int seg = rem & 3;
            int g   = rowIdx[r];
            const uint16_t* base = p ? g_aevL : g_aevH;
            const uint16_t* src  = base + ((size_t)(g < 0 ? 0 : g) * KPAD1 + kc * 32 + seg * 8);
            cp16(smem_base + APL(b, p) + (r * 40 + seg * 8) * 2, src, g >= 0 ? 16 : 0);
        }
    };
    auto issueB1 = [&](int kc, int b) {
        #pragma unroll
        for (int it = 0; it < 8; ++it) {
            int t = tid + it * 256;          // 0..2047
            int p   = t >> 10;
            int rem = t & 1023;
            int n   = rem >> 2;
            int seg = rem & 3;
            const uint16_t* base = p ? g_w1L : g_w1H;
            cp16(smem_base + BPL(b, p) + (n * 40 + seg * 8) * 2,
                 base + ((size_t)(se * D1 + n) * KPAD1 + kc * 32 + seg * 8), 16);
        }
        CP_COMMIT();
    };
    auto issueW2 = [&](int kc, int b) {
        #pragma unroll
        for (int it = 0; it < 6; ++it) {
            int t = tid + it * 256;          // 0..1535
            int p   = t >= 768;
            int rem = t - p * 768;
            int n   = rem >> 2;
            int seg = rem & 3;
            const uint16_t* base = p ? g_w2L : g_w2H;
            cp16(smem_base + WPL(b, p) + (n * 40 + seg * 8) * 2,
                 base + ((size_t)(se * D2 + n) * D1 + kc * 32 + seg * 8), 16);
        }
        CP_COMMIT();
    };
    auto issueW3 = [&](int kc, int b) {
        #pragma unroll
        for (int it = 0; it < 5; ++it) {
            int t = tid + it * 256;          // 0..1279
            int p   = t >= 640;
            int rem = t - p * 640;
            int n   = rem >> 2;
            int seg = rem & 3;
            const uint16_t* base = p ? g_w3L : g_w3H;
            cp16(smem_base + WPL(b, p) + (n * 40 + seg * 8) * 2,
                 base + ((size_t)(se * D3 + n) * D2 + kc * 32 + seg * 8), 16);
        }
        CP_COMMIT();
    };

    // ==================== Layer 1: [128 x 1024] @ [1024 x 256] ====================
    {
        const int nB = wn * 64;
        float acc[4][8][4];
        #pragma unroll
        for (int mi = 0; mi < 4; mi++)
            #pragma unroll
            for (int j = 0; j < 8; j++)
                #pragma unroll
                for (int q = 0; q < 4; q++) acc[mi][j][q] = 0.f;

        issueA1(0, 0); issueB1(0, 0);
        for (int kc = 0; kc < NC1; ++kc) {
            if (kc + 1 < NC1) {
                int nb = (kc + 1) & 1;
                issueA1(kc + 1, nb); issueB1(kc + 1, nb);
                CP_WAIT1();
            } else CP_WAIT0();
            __syncthreads();
            const int b = kc & 1;
            #pragma unroll
            for (int ks = 0; ks < 2; ++ks) {
                const int k0 = ks * 16;
                uint32_t AH[4][4], AL[4][4];
                #pragma unroll
                for (int mi = 0; mi < 4; mi++) {
                    uint32_t aaddr = smem_base + APL(b, 0)
                                   + ((mB + mi * 16 + amrow) * 40 + k0 + akoff) * 2;
                    ldm4(AH[mi], aaddr);
                    ldm4(AL[mi], aaddr + 10240);
                }
                #pragma unroll
                for (int jp = 0; jp < 4; ++jp) {
                    uint32_t baddr = smem_base + BPL(b, 0)
                                   + ((nB + jp * 16 + bnrow) * 40 + k0 + bkoff) * 2;
                    uint32_t BH[4], BL[4];
                    ldm4(BH, baddr);
                    ldm4(BL, baddr + 20480);
                    #pragma unroll
                    for (int mi = 0; mi < 4; mi++) {
                        mma16(acc[mi][2 * jp],     AH[mi], BH);
                        mma16(acc[mi][2 * jp],     AL[mi], BH);
                        mma16(acc[mi][2 * jp],     AH[mi], BL);
                        mma16(acc[mi][2 * jp + 1], AH[mi], BH + 2);
                        mma16(acc[mi][2 * jp + 1], AL[mi], BH + 2);
                        mma16(acc[mi][2 * jp + 1], AH[mi], BL + 2);
                    }
                }
            }
            __syncthreads();
        }
        // start W2 staging early (overlaps epilogue)
        issueW2(0, 0);
        // epilogue: bias + CELU -> bf16 h planes
        #pragma unroll
        for (int mi = 0; mi < 4; mi++) {
            int r0 = mB + mi * 16 + gid;
            int r1 = r0 + 8;
            #pragma unroll
            for (int j = 0; j < 8; j++) {
                int c = nB + j * 8 + tig * 2;
                float bb0 = __ldg(b1g + c), bb1 = __ldg(b1g + c + 1);
                float v00 = celu01(acc[mi][j][0] + bb0);
                float v01 = celu01(acc[mi][j][1] + bb1);
                float v10 = celu01(acc[mi][j][2] + bb0);
                float v11 = celu01(acc[mi][j][3] + bb1);
                uint32_t h0 = cvt2(v00, v01);
                uint32_t l0 = cvt2(v00 - lo16f(h0), v01 - hi16f(h0));
                uint32_t h1 = cvt2(v10, v11);
                uint32_t l1 = cvt2(v10 - lo16f(h1), v11 - hi16f(h1));
                *(uint32_t*)(smc + HH + (r0 * 264 + c) * 2) = h0;
                *(uint32_t*)(smc + HL + (r0 * 264 + c) * 2) = l0;
                *(uint32_t*)(smc + HH + (r1 * 264 + c) * 2) = h1;
                *(uint32_t*)(smc + HL + (r1 * 264 + c) * 2) = l1;
            }
        }
    }

    // ==================== Layer 2: [128 x 256] @ [256 x 192] ====================
    {
        const int nB = wn * 48;
        float acc[4][6][4];
        #pragma unroll
        for (int mi = 0; mi < 4; mi++)
            #pragma unroll
            for (int j = 0; j < 6; j++)
                #pragma unroll
                for (int q = 0; q < 4; q++) acc[mi][j][q] = 0.f;

        for (int kc = 0; kc < NC2; ++kc) {
            if (kc + 1 < NC2) { issueW2(kc + 1, (kc + 1) & 1); CP_WAIT1(); }
            else              { CP_WAIT0(); }
            __syncthreads();
            const int b = kc & 1;
            #pragma unroll
            for (int ks = 0; ks < 2; ++ks) {
                const int kg0 = kc * 32 + ks * 16;
                uint32_t AH[4][4], AL[4][4];
                #pragma unroll
                for (int mi = 0; mi < 4; mi++) {
                    uint32_t aaddr = smem_base + HH
                                   + ((mB + mi * 16 + amrow) * 264 + kg0 + akoff) * 2;
                    ldm4(AH[mi], aaddr);
                    ldm4(AL[mi], aaddr + 67584);
                }
                #pragma unroll
                for (int jp = 0; jp < 3; ++jp) {
                    uint32_t baddr = smem_base + WPL(b, 0)
                                   + ((nB + jp * 16 + bnrow) * 40 + ks * 16 + bkoff) * 2;
                    uint32_t BH[4], BL[4];
                    ldm4(BH, baddr);
                    ldm4(BL, baddr + 15360);
                    #pragma unroll
                    for (int mi = 0; mi < 4; mi++) {
                        mma16(acc[mi][2 * jp],     AH[mi], BH);
                        mma16(acc[mi][2 * jp],     AL[mi], BH);
                        mma16(acc[mi][2 * jp],     AH[mi], BL);
                        mma16(acc[mi][2 * jp + 1], AH[mi], BH + 2);
                        mma16(acc[mi][2 * jp + 1], AL[mi], BH + 2);
                        mma16(acc[mi][2 * jp + 1], AH[mi], BL + 2);
                    }
                }
            }
            __syncthreads();
        }
        issueW3(0, 0);
        // epilogue -> h2 planes (cols 0..191, same region)
        #pragma unroll
        for (int mi = 0; mi < 4; mi++) {
            int r0 = mB + mi * 16 + gid;
            int r1 = r0 + 8;
            #pragma unroll
            for (int j = 0; j < 6; j++) {
                int c = nB + j * 8 + tig * 2;
                float bb0 = __ldg(b2g + c), bb1 = __ldg(b2g + c + 1);
                float v00 = celu01(acc[mi][j][0] + bb0);
                float v01 = celu01(acc[mi][j][1] + bb1);
                float v10 = celu01(acc[mi][j][2] + bb0);
                float v11 = celu01(acc[mi][j][3] + bb1);
                uint32_t h0 = cvt2(v00, v01);
                uint32_t l0 = cvt2(v00 - lo16f(h0), v01 - hi16f(h0));
                uint32_t h1 = cvt2(v10, v11);
                uint32_t l1 = cvt2(v10 - lo16f(h1), v11 - hi16f(h1));
                *(uint32_t*)(smc + HH + (r0 * 264 + c) * 2) = h0;
                *(uint32_t*)(smc + HL + (r0 * 264 + c) * 2) = l0;
                *(uint32_t*)(smc + HH + (r1 * 264 + c) * 2) = h1;
                *(uint32_t*)(smc + HL + (r1 * 264 + c) * 2) = l1;
            }
        }
    }

    // ==================== Layer 3: [128 x 192] @ [192 x 160] ====================
    float energy = 0.f;
    {
        const int nB = wn * 40;
        float acc[4][5][4];
        #pragma unroll
        for (int mi = 0; mi < 4; mi++)
            #pragma unroll
            for (int j = 0; j < 5; j++)
                #pragma unroll
                for (int q = 0; q < 4; q++) acc[mi][j][q] = 0.f;

        for (int kc = 0; kc < NC3; ++kc) {
            if (kc + 1 < NC3) { issueW3(kc + 1, (kc + 1) & 1); CP_WAIT1(); }
            else              { CP_WAIT0(); }
            __syncthreads();
            const int b = kc & 1;
            #pragma unroll
            for (int ks = 0; ks < 2; ++ks) {
                const int kg0 = kc * 32 + ks * 16;
                uint32_t AH[4][4], AL[4][4];
                #pragma unroll
                for (int mi = 0; mi < 4; mi++) {
                    uint32_t aaddr = smem_base + HH
                                   + ((mB + mi * 16 + amrow) * 264 + kg0 + akoff) * 2;
                    ldm4(AH[mi], aaddr);
                    ldm4(AL[mi], aaddr + 67584);
                }
                #pragma unroll
                for (int jp = 0; jp < 2; ++jp) {
                    uint32_t baddr = smem_base + WPL(b, 0)
                                   + ((nB + jp * 16 + bnrow) * 40 + ks * 16 + bkoff) * 2;
                    uint32_t BH[4], BL[4];
                    ldm4(BH, baddr);
                    ldm4(BL, baddr + 15360);
                    #pragma unroll
                    for (int mi = 0; mi < 4; mi++) {
                        mma16(acc[mi][2 * jp],     AH[mi], BH);
                        mma16(acc[mi][2 * jp],     AL[mi], BH);
                        mma16(acc[mi][2 * jp],     AH[mi], BL);
                        mma16(acc[mi][2 * jp + 1], AH[mi], BH + 2);
                        mma16(acc[mi][2 * jp + 1], AL[mi], BH + 2);
                        mma16(acc[mi][2 * jp + 1], AH[mi], BL + 2);
                    }
                }
                {   // j = 4 (single octet) via ldmatrix.x2
                    uint32_t baddr = smem_base + WPL(b, 0)
                                   + ((nB + 32 + (lane & 7)) * 40 + ks * 16 + bkoff) * 2;
                    uint32_t BH[2], BL[2];
                    ldm2(BH, baddr);
                    ldm2(BL, baddr + 15360);
                    #pragma unroll
                    for (int mi = 0; mi < 4; mi++) {
                        mma16(acc[mi][4], AH[mi], BH);
                        mma16(acc[mi][4], AL[mi], BH);
                        mma16(acc[mi][4], AH[mi], BL);
                    }
                }
            }
            __syncthreads();
        }
        // epilogue: bias + CELU, dot with w4, row-masked
        #pragma unroll
        for (int mi = 0; mi < 4; mi++) {
            int r0 = mB + mi * 16 + gid;
            int r1 = r0 + 8;
            #pragma unroll
            for (int j = 0; j < 5; j++) {
                int n = nB + j * 8 + tig * 2;
                float bb0 = __ldg(b3g + n), bb1 = __ldg(b3g + n + 1);
                float w0  = __ldg(w4g + n), w1  = __ldg(w4g + n + 1);
                if (r0 < valid)
                    energy += celu01(acc[mi][j][0] + bb0) * w0
                            + celu01(acc[mi][j][1] + bb1) * w1;
                if (r1 < valid)
                    energy += celu01(acc[mi][j][2] + bb0) * w0
                            + celu01(acc[mi][j][3] + bb1) * w1;
            }
        }
    }

    red[tid] = energy;
    __syncthreads();
    #pragma unroll
    for (int st = 128; st > 0; st >>= 1) {
        if (tid < st) red[tid] += red[tid + st];
        __syncthreads();
    }
    if (tid == 0)
        atomicAdd(&g_scratch, (double)(red[0] + (float)valid * B4[se]));
}

__global__ void init_kernel() { g_scratch = 0.0; }
__global__ void fin_kernel(float* out) { out[0] = (float)(g_scratch * (1.0 / ENS)); }

extern "C" void kernel_launch(void* const* d_in, const int* in_sizes, int n_in,
                              void* d_out, int out_size)
{
    // Identify inputs by element count (robust to metadata ordering).
    const float *aev = 0, *W1 = 0, *B1 = 0, *W2 = 0, *B2 = 0,
                *W3 = 0, *B3 = 0, *W4 = 0, *B4 = 0;
    const int *idx = 0;
    int n5120 = 0, n50000 = 0;
    for (int i = 0; i < n_in; ++i) {
        switch (in_sizes[i]) {
            case 50400000: aev = (const float*)d_in[i]; break;
            case 8257536:  W1  = (const float*)d_in[i]; break;
            case 8192:     B1  = (const float*)d_in[i]; break;
            case 1572864:  W2  = (const float*)d_in[i]; break;
            case 6144:     B2  = (const float*)d_in[i]; break;
            case 983040:   W3  = (const float*)d_in[i]; break;
            case 5120:
                if (n5120++ == 0) B3 = (const float*)d_in[i];
                else              W4 = (const float*)d_in[i];
                break;
            case 32:       B4  = (const float*)d_in[i]; break;
            case 50000:
                if (n50000++ == 0) { /* species (unused) */ }
                else idx = (const int*)d_in[i];
                break;
            default: break;
        }
    }

    cudaFuncSetAttribute(ani_main,
                         cudaFuncAttributeMaxDynamicSharedMemorySize, SMEM_BYTES);

    init_kernel<<<1, 1>>>();

    // pre-pass: build bf16 hi/lo planes in persistent scratch
    prep_aev<<<(NATOM * (KPAD1 / 2) + 255) / 256, 256>>>(aev);
    {
        uint16_t *w1H = 0, *w1L = 0, *w2H = 0, *w2L = 0, *w3H = 0, *w3L = 0;
        cudaGetSymbolAddress((void**)&w1H, g_w1H);
        cudaGetSymbolAddress((void**)&w1L, g_w1L);
        cudaGetSymbolAddress((void**)&w2H, g_w2H);
        cudaGetSymbolAddress((void**)&w2L, g_w2L);
        cudaGetSymbolAddress((void**)&w3H, g_w3H);
        cudaGetSymbolAddress((void**)&w3L, g_w3L);
        prep_w<<<(NSE * D1 * (KPAD1 / 2) + 255) / 256, 256>>>(W1, w1H, w1L, AEVD, D1, KPAD1);
        prep_w<<<(NSE * D2 * (D1 / 2)   + 255) / 256, 256>>>(W2, w2H, w2L, D1,   D2, D1);
        prep_w<<<(NSE * D3 * (D2 / 2)   + 255) / 256, 256>>>(W3, w3H, w3L, D2,   D3, D2);
    }

    dim3 grid(ENS, NTILES, NSPECIES);
    ani_main<<<grid, 256, SMEM_BYTES>>>(B1, B2, B3, W4, B4, idx);
    fin_kernel<<<1, 1>>>((float*)d_out);
}